// round 9
// baseline (speedup 1.0000x reference)
#include <cuda_runtime.h>
#include <cuda_bf16.h>

// RobustSum L1 IRLS (K=3): x(128,1024) @ W(1024,1024) -> z(128,1024), fp32.
//
// Per (b,o): c = z/D1; t_i = fma(x_i, W_io, -c); r_i = 1/(|t_i|+eps) [MUFU];
// q = sum r*t, sw = sum r;  c' = (q + c*sw)/max(sw,1e-12);  out = D1*c.
//
// R9: minimize warp-instructions (empirical issue ceiling ~63-68% makes time
// track instruction count). Thread = 2b x 4o x 128i: 1 LDG.128 + 1 LDS.64
// (x interleaved pair) serves 8 element-ops -> ~5.25 instr/element (R6: 6.25).
// Block = 256 thr = 8 warps = 8 i-chunks; block covers 2b x 128o.
// Grid (8,64) = 512 blocks, launch_bounds(256,4): 4 CTAs/SM, one wave.

#define DIN     1024
#define DOUT    1024
#define KITER   3
#define EPSILON 0.001f
#define ICHUNK  128
#define NTHREADS 256

typedef unsigned long long ull;

__device__ __forceinline__ ull pack2(float lo, float hi) {
    ull r; asm("mov.b64 %0, {%1,%2};" : "=l"(r) : "f"(lo), "f"(hi)); return r;
}
__device__ __forceinline__ void unpack2(ull v, float& lo, float& hi) {
    asm("mov.b64 {%0,%1}, %2;" : "=f"(lo), "=f"(hi) : "l"(v));
}
__device__ __forceinline__ ull fma2(ull a, ull b, ull c) {
    ull r; asm("fma.rn.f32x2 %0, %1, %2, %3;" : "=l"(r) : "l"(a), "l"(b), "l"(c)); return r;
}
__device__ __forceinline__ ull add2(ull a, ull b) {
    ull r; asm("add.rn.f32x2 %0, %1, %2;" : "=l"(r) : "l"(a), "l"(b)); return r;
}
__device__ __forceinline__ float rcpf(float a) {
    float r; asm("rcp.approx.f32 %0, %1;" : "=f"(r) : "f"(a)); return r;
}

__global__ __launch_bounds__(NTHREADS, 4)
void robust_sum_kernel(const float* __restrict__ x,
                       const float* __restrict__ w,
                       float* __restrict__ out)
{
    __shared__ float2 xs2[DIN];            // 8 KB: interleaved {x[b0][i], x[b1][i]}
    __shared__ ull red[8][32][8];          // 16 KB: [iq][lane][payload]

    const int tid  = threadIdx.x;
    const int iq   = tid >> 5;             // warp == i-chunk 0..7 (128 i each)
    const int lane = tid & 31;
    const int o0   = blockIdx.x * 128 + lane * 4;
    const int b0   = blockIdx.y * 2;

    // Stage x as interleaved pairs (coalesced per-row reads).
    for (int t = tid; t < DIN; t += NTHREADS) {
        float a = x[(size_t)b0 * DIN + t];
        float b = x[(size_t)(b0 + 1) * DIN + t];
        xs2[t] = make_float2(a, b);
    }
    __syncthreads();

    const float2* xp    = &xs2[iq * ICHUNK];
    const float*  wbase = w + (size_t)(iq * ICHUNK) * DOUT + o0;

    // ---- pass 0: z = x @ W (as c = z/DIN), fully packed ----
    ull s01a = 0ULL, s23a = 0ULL, s01b = 0ULL, s23b = 0ULL;
    #pragma unroll 4
    for (int i = 0; i < ICHUNK; i++) {
        ulonglong2 wv = __ldg((const ulonglong2*)(wbase + (size_t)i * DOUT));
        float2 xv = xp[i];
        ull xa = pack2(xv.x, xv.x);
        ull xb = pack2(xv.y, xv.y);
        s01a = fma2(xa, wv.x, s01a);
        s23a = fma2(xa, wv.y, s23a);
        s01b = fma2(xb, wv.x, s01b);
        s23b = fma2(xb, wv.y, s23b);
    }
    {
        ull* rp = red[iq][lane];
        ((ulonglong2*)rp)[0] = make_ulonglong2(s01a, s23a);
        ((ulonglong2*)rp)[1] = make_ulonglong2(s01b, s23b);
    }
    __syncthreads();
    float c0a, c1a, c2a, c3a, c0b, c1b, c2b, c3b;
    {
        ull a0 = 0ULL, a1 = 0ULL, a2 = 0ULL, a3 = 0ULL;
        #pragma unroll
        for (int j = 0; j < 8; j++) {
            const ull* rp = red[j][lane];
            ulonglong2 v0 = ((const ulonglong2*)rp)[0];
            ulonglong2 v1 = ((const ulonglong2*)rp)[1];
            a0 = add2(a0, v0.x);  a1 = add2(a1, v0.y);
            a2 = add2(a2, v1.x);  a3 = add2(a3, v1.y);
        }
        unpack2(a0, c0a, c1a);  unpack2(a1, c2a, c3a);
        unpack2(a2, c0b, c1b);  unpack2(a3, c2b, c3b);
        const float inv = 1.0f / DIN;
        c0a *= inv; c1a *= inv; c2a *= inv; c3a *= inv;
        c0b *= inv; c1b *= inv; c2b *= inv; c3b *= inv;
    }

    // ---- K IRLS iterations ----
    #pragma unroll 1
    for (int k = 0; k < KITER; k++) {
        const float n0a = -c0a, n1a = -c1a, n2a = -c2a, n3a = -c3a;
        const float n0b = -c0b, n1b = -c1b, n2b = -c2b, n3b = -c3b;
        ull q01a = 0ULL, q23a = 0ULL, q01b = 0ULL, q23b = 0ULL;
        ull w01a = 0ULL, w23a = 0ULL, w01b = 0ULL, w23b = 0ULL;
        #pragma unroll 2
        for (int i = 0; i < ICHUNK; i++) {
            float4 wv = __ldg((const float4*)(wbase + (size_t)i * DOUT));
            float2 xv = xp[i];
            // b0
            float t0 = fmaf(xv.x, wv.x, n0a);
            float t1 = fmaf(xv.x, wv.y, n1a);
            float t2 = fmaf(xv.x, wv.z, n2a);
            float t3 = fmaf(xv.x, wv.w, n3a);
            float r0 = rcpf(fabsf(t0) + EPSILON);
            float r1 = rcpf(fabsf(t1) + EPSILON);
            float r2 = rcpf(fabsf(t2) + EPSILON);
            float r3 = rcpf(fabsf(t3) + EPSILON);
            ull r01 = pack2(r0, r1), r23 = pack2(r2, r3);
            q01a = fma2(r01, pack2(t0, t1), q01a);
            q23a = fma2(r23, pack2(t2, t3), q23a);
            w01a = add2(w01a, r01);
            w23a = add2(w23a, r23);
            // b1
            float u0 = fmaf(xv.y, wv.x, n0b);
            float u1 = fmaf(xv.y, wv.y, n1b);
            float u2 = fmaf(xv.y, wv.z, n2b);
            float u3 = fmaf(xv.y, wv.w, n3b);
            float p0 = rcpf(fabsf(u0) + EPSILON);
            float p1 = rcpf(fabsf(u1) + EPSILON);
            float p2 = rcpf(fabsf(u2) + EPSILON);
            float p3 = rcpf(fabsf(u3) + EPSILON);
            ull p01 = pack2(p0, p1), p23 = pack2(p2, p3);
            q01b = fma2(p01, pack2(u0, u1), q01b);
            q23b = fma2(p23, pack2(u2, u3), q23b);
            w01b = add2(w01b, p01);
            w23b = add2(w23b, p23);
        }
        __syncthreads();               // previous reduce reads done
        {
            ull* rp = red[iq][lane];
            ((ulonglong2*)rp)[0] = make_ulonglong2(q01a, q23a);
            ((ulonglong2*)rp)[1] = make_ulonglong2(q01b, q23b);
            ((ulonglong2*)rp)[2] = make_ulonglong2(w01a, w23a);
            ((ulonglong2*)rp)[3] = make_ulonglong2(w01b, w23b);
        }
        __syncthreads();
        ull qa0 = 0ULL, qa1 = 0ULL, qb0 = 0ULL, qb1 = 0ULL;
        ull wa0 = 0ULL, wa1 = 0ULL, wb0 = 0ULL, wb1 = 0ULL;
        #pragma unroll
        for (int j = 0; j < 8; j++) {
            const ull* rp = red[j][lane];
            ulonglong2 v0 = ((const ulonglong2*)rp)[0];
            ulonglong2 v1 = ((const ulonglong2*)rp)[1];
            ulonglong2 v2 = ((const ulonglong2*)rp)[2];
            ulonglong2 v3 = ((const ulonglong2*)rp)[3];
            qa0 = add2(qa0, v0.x);  qa1 = add2(qa1, v0.y);
            qb0 = add2(qb0, v1.x);  qb1 = add2(qb1, v1.y);
            wa0 = add2(wa0, v2.x);  wa1 = add2(wa1, v2.y);
            wb0 = add2(wb0, v3.x);  wb1 = add2(wb1, v3.y);
        }
        float q0, q1, s0, s1;
        unpack2(qa0, q0, q1);  unpack2(wa0, s0, s1);
        c0a = __fdividef(fmaf(c0a, s0, q0), fmaxf(s0, 1e-12f));
        c1a = __fdividef(fmaf(c1a, s1, q1), fmaxf(s1, 1e-12f));
        unpack2(qa1, q0, q1);  unpack2(wa1, s0, s1);
        c2a = __fdividef(fmaf(c2a, s0, q0), fmaxf(s0, 1e-12f));
        c3a = __fdividef(fmaf(c3a, s1, q1), fmaxf(s1, 1e-12f));
        unpack2(qb0, q0, q1);  unpack2(wb0, s0, s1);
        c0b = __fdividef(fmaf(c0b, s0, q0), fmaxf(s0, 1e-12f));
        c1b = __fdividef(fmaf(c1b, s1, q1), fmaxf(s1, 1e-12f));
        unpack2(qb1, q0, q1);  unpack2(wb1, s0, s1);
        c2b = __fdividef(fmaf(c2b, s0, q0), fmaxf(s0, 1e-12f));
        c3b = __fdividef(fmaf(c3b, s1, q1), fmaxf(s1, 1e-12f));
    }

    if (iq == 0) {
        const float D = (float)DIN;
        *(float4*)(out + (size_t)(b0 + 0) * DOUT + o0) =
            make_float4(D * c0a, D * c1a, D * c2a, D * c3a);
        *(float4*)(out + (size_t)(b0 + 1) * DOUT + o0) =
            make_float4(D * c0b, D * c1b, D * c2b, D * c3b);
    }
}

extern "C" void kernel_launch(void* const* d_in, const int* in_sizes, int n_in,
                              void* d_out, int out_size)
{
    const float* x = (const float*)d_in[0];   // (128, 1024)
    const float* w = (const float*)d_in[1];   // (1024, 1024)
    float* out = (float*)d_out;               // (128, 1024)

    dim3 grid(DOUT / 128, 128 / 2);           // (8, 64) = 512 blocks
    robust_sum_kernel<<<grid, NTHREADS>>>(x, w, out);
}

// round 10
// speedup vs baseline: 1.2630x; 1.2630x over previous
#include <cuda_runtime.h>
#include <cuda_bf16.h>

// RobustSum L1 IRLS (K=3): x(128,1024) @ W(1024,1024) -> z(128,1024), fp32.
//
// Identity per (b,o): c = z/D1; t_i = x_i*W_io - c; r_i = 1/(|t_i|+eps);
// q = sum r_i t_i, sw = sum r_i; c' = (q + c*sw)/max(sw,1e-12); out = D1*c.
//
// R10 key change — HALVE MUFU (rt=8/SMSP was the issue-ceiling culprit):
// pair consecutive i's: with d = |t|+eps,
//   1/d_i + 1/d_j         = (d_i+d_j) * rcp(d_i*d_j)
//   t_i/d_i + t_j/d_j     = (t_i*d_j + t_j*d_i) * rcp(d_i*d_j)
// -> ONE MUFU.RCP per 2 elements; extra muls go to fma pipe as packed f32x2,
// |t| via 64-bit AND on the alu pipe (underused).
//
// Thread = 1b x 4o (two f32x2 lanes: o01, o23) x 256i stepped by 2.
// Block = 128 thr = 4 warps (warp = i-chunk of 256); block = 1b x 128o.
// Grid (8,128) = 1024 blocks, one wave (R6's proven shape).

#define DIN     1024
#define DOUT    1024
#define KITER   3
#define EPSILON 0.001f
#define ICHUNK  256
#define NTHREADS 128

typedef unsigned long long ull;

__device__ __forceinline__ ull pack2(float lo, float hi) {
    ull r; asm("mov.b64 %0, {%1,%2};" : "=l"(r) : "f"(lo), "f"(hi)); return r;
}
__device__ __forceinline__ void unpack2(ull v, float& lo, float& hi) {
    asm("mov.b64 {%0,%1}, %2;" : "=f"(lo), "=f"(hi) : "l"(v));
}
__device__ __forceinline__ ull fma2(ull a, ull b, ull c) {
    ull r; asm("fma.rn.f32x2 %0, %1, %2, %3;" : "=l"(r) : "l"(a), "l"(b), "l"(c)); return r;
}
__device__ __forceinline__ ull add2(ull a, ull b) {
    ull r; asm("add.rn.f32x2 %0, %1, %2;" : "=l"(r) : "l"(a), "l"(b)); return r;
}
__device__ __forceinline__ ull mul2(ull a, ull b) {
    ull r; asm("mul.rn.f32x2 %0, %1, %2;" : "=l"(r) : "l"(a), "l"(b)); return r;
}
__device__ __forceinline__ float rcpf(float a) {
    float r; asm("rcp.approx.f32 %0, %1;" : "=f"(r) : "f"(a)); return r;
}
__device__ __forceinline__ ull rcp2(ull m) {   // lane-wise rcp of packed pair
    float a, b; unpack2(m, a, b);
    return pack2(rcpf(a), rcpf(b));
}

#define ABSM 0x7FFFFFFF7FFFFFFFULL

__global__ __launch_bounds__(NTHREADS, 8)
void robust_sum_kernel(const float* __restrict__ x,
                       const float* __restrict__ w,
                       float* __restrict__ out)
{
    __shared__ float xs[DIN];              // 4 KB: 1 b-row
    __shared__ ull red[4][32][4];          // 4 KB: [iq][lane]{q01,q23,sw01,sw23}

    const int tid  = threadIdx.x;
    const int iq   = tid >> 5;             // warp == i-chunk 0..3 (256 i each)
    const int lane = tid & 31;
    const int o0   = blockIdx.x * 128 + lane * 4;
    const int b    = blockIdx.y;

    // Stage x row, coalesced float4.
    {
        const float4* src = (const float4*)(x + (size_t)b * DIN);
        float4*       dst = (float4*)xs;
        #pragma unroll
        for (int t = tid; t < DIN / 4; t += NTHREADS)
            dst[t] = src[t];
    }
    __syncthreads();

    const float* xr    = &xs[iq * ICHUNK];
    const float* wbase = w + (size_t)(iq * ICHUNK) * DOUT + o0;

    // ---- pass 0: z = x @ W (as c = z/DIN), packed ----
    ull s01 = 0ULL, s23 = 0ULL;
    #pragma unroll 4
    for (int i = 0; i < ICHUNK; i++) {
        ulonglong2 wv = __ldg((const ulonglong2*)(wbase + (size_t)i * DOUT));
        float xi = xr[i];
        ull xd = pack2(xi, xi);
        s01 = fma2(xd, wv.x, s01);
        s23 = fma2(xd, wv.y, s23);
    }
    red[iq][lane][0] = s01;
    red[iq][lane][1] = s23;
    __syncthreads();
    float c0, c1, c2, c3;
    {
        ull a0 = 0ULL, a1 = 0ULL;
        #pragma unroll
        for (int j = 0; j < 4; j++) {
            a0 = add2(a0, red[j][lane][0]);
            a1 = add2(a1, red[j][lane][1]);
        }
        unpack2(a0, c0, c1);
        unpack2(a1, c2, c3);
        const float inv = 1.0f / DIN;
        c0 *= inv; c1 *= inv; c2 *= inv; c3 *= inv;
    }

    const ull EPS2 = pack2(EPSILON, EPSILON);

    // ---- K IRLS iterations, i paired (1 MUFU per 2 elements) ----
    #pragma unroll 1
    for (int k = 0; k < KITER; k++) {
        const ull nc01 = pack2(-c0, -c1);
        const ull nc23 = pack2(-c2, -c3);
        ull q01 = 0ULL, q23 = 0ULL, sw01 = 0ULL, sw23 = 0ULL;
        #pragma unroll 2
        for (int i = 0; i < ICHUNK; i += 2) {
            ulonglong2 wva = __ldg((const ulonglong2*)(wbase + (size_t)i * DOUT));
            ulonglong2 wvb = __ldg((const ulonglong2*)(wbase + (size_t)(i + 1) * DOUT));
            float2 xv = *(const float2*)(xr + i);
            ull xa = pack2(xv.x, xv.x);
            ull xb = pack2(xv.y, xv.y);
            // t = xw - c for the two i's, packed over (o0,o1) and (o2,o3)
            ull ta01 = fma2(xa, wva.x, nc01);
            ull ta23 = fma2(xa, wva.y, nc23);
            ull tb01 = fma2(xb, wvb.x, nc01);
            ull tb23 = fma2(xb, wvb.y, nc23);
            // d = |t| + eps  (abs = 64-bit AND on alu pipe)
            ull da01 = add2(ta01 & ABSM, EPS2);
            ull da23 = add2(ta23 & ABSM, EPS2);
            ull db01 = add2(tb01 & ABSM, EPS2);
            ull db23 = add2(tb23 & ABSM, EPS2);
            // pair-combine: m = da*db, s = da+db, cross = ta*db + tb*da
            ull m01 = mul2(da01, db01);
            ull m23 = mul2(da23, db23);
            ull sp01 = add2(da01, db01);
            ull sp23 = add2(da23, db23);
            ull cr01 = fma2(ta01, db01, mul2(tb01, da01));
            ull cr23 = fma2(ta23, db23, mul2(tb23, da23));
            // single rcp per pair (2 MUFU per packed reg = 4 per 8 elements)
            ull r01 = rcp2(m01);
            ull r23 = rcp2(m23);
            // accumulate: q += cross*r, sw += s*r
            q01  = fma2(cr01, r01, q01);
            q23  = fma2(cr23, r23, q23);
            sw01 = fma2(sp01, r01, sw01);
            sw23 = fma2(sp23, r23, sw23);
        }
        __syncthreads();               // previous reduce reads done
        {
            ull* rp = red[iq][lane];
            rp[0] = q01;  rp[1] = q23;
            rp[2] = sw01; rp[3] = sw23;
        }
        __syncthreads();
        ull qa = 0ULL, qb = 0ULL, wa = 0ULL, wb = 0ULL;
        #pragma unroll
        for (int j = 0; j < 4; j++) {
            const ull* rp = red[j][lane];
            qa = add2(qa, rp[0]);
            qb = add2(qb, rp[1]);
            wa = add2(wa, rp[2]);
            wb = add2(wb, rp[3]);
        }
        float q0f, q1f, w0f, w1f;
        unpack2(qa, q0f, q1f);  unpack2(wa, w0f, w1f);
        c0 = __fdividef(fmaf(c0, w0f, q0f), fmaxf(w0f, 1e-12f));
        c1 = __fdividef(fmaf(c1, w1f, q1f), fmaxf(w1f, 1e-12f));
        unpack2(qb, q0f, q1f);  unpack2(wb, w0f, w1f);
        c2 = __fdividef(fmaf(c2, w0f, q0f), fmaxf(w0f, 1e-12f));
        c3 = __fdividef(fmaf(c3, w1f, q1f), fmaxf(w1f, 1e-12f));
    }

    if (iq == 0) {
        const float D = (float)DIN;
        *(float4*)(out + (size_t)b * DOUT + o0) =
            make_float4(D * c0, D * c1, D * c2, D * c3);
    }
}

extern "C" void kernel_launch(void* const* d_in, const int* in_sizes, int n_in,
                              void* d_out, int out_size)
{
    const float* x = (const float*)d_in[0];   // (128, 1024)
    const float* w = (const float*)d_in[1];   // (1024, 1024)
    float* out = (float*)d_out;               // (128, 1024)

    dim3 grid(DOUT / 128, 128);               // (8, 128) = 1024 blocks
    robust_sum_kernel<<<grid, NTHREADS>>>(x, w, out);
}